// round 1
// baseline (speedup 1.0000x reference)
#include <cuda_runtime.h>

// GazeLSTM: N=8192 rows (B*T), L=32 steps, H=256, 4H=1024, IN=2, OUT=128.
// Persistent-state kernel: 128 CTAs x 256 threads, each CTA owns 64 rows.
// h double-buffered in smem, c in smem, W_hh staged in smem k-panels.

#define Hh      256
#define FOURH   1024
#define LSTEPS  32
#define NB      64        // rows per CTA
#define NCTA    128       // 8192 / 64
#define PADK    257       // h row pitch (odd pad: conflict-free col reads & row writes)
#define KT      64        // k-tile for W panel staging
#define OUTD    128

// ---- prologue-built weight layouts (module-scope device memory; no runtime alloc) ----
__device__ float g_Wt[Hh * FOURH];    // Wt[k][j*4+q] = W_hh[(q*256+j)][k]
__device__ float g_bias[FOURH];       // bias[j*4+q]  = b_ih[g] + b_hh[g]
__device__ float g_Wihp[FOURH * 2];   // Wihp[j*4+q][s] = W_ih[g][s]
__device__ float g_fcT[Hh * OUTD];    // fcT[k][o] = fc_w[o][k]

__global__ void prep_kernel(const float* __restrict__ W_ih,
                            const float* __restrict__ W_hh,
                            const float* __restrict__ b_ih,
                            const float* __restrict__ b_hh,
                            const float* __restrict__ fc_w) {
    int idx = blockIdx.x * blockDim.x + threadIdx.x;
    int stride = gridDim.x * blockDim.x;
    for (int e = idx; e < Hh * FOURH; e += stride) {
        int k = e >> 10, jq = e & 1023;
        int j = jq >> 2, q = jq & 3;
        g_Wt[e] = W_hh[(q * Hh + j) * Hh + k];
    }
    for (int e = idx; e < Hh * OUTD; e += stride) {
        int k = e >> 7, o = e & 127;
        g_fcT[e] = fc_w[o * Hh + k];
    }
    if (idx < FOURH) {
        int j = idx >> 2, q = idx & 3;
        int g = q * Hh + j;
        g_bias[idx]        = b_ih[g] + b_hh[g];
        g_Wihp[idx * 2 + 0] = W_ih[g * 2 + 0];
        g_Wihp[idx * 2 + 1] = W_ih[g * 2 + 1];
    }
}

__device__ __forceinline__ float sigf(float v) {
    return __fdividef(1.0f, 1.0f + __expf(-v));
}
__device__ __forceinline__ float tanhfast(float v) {
    float e = __expf(-2.0f * v);                 // |arg| bounded (~34), no overflow
    return __fdividef(1.0f - e, 1.0f + e);
}

// smem floats: H double buffer 2*64*257 = 32896, W panel 64*128 = 8192, C 64*256 = 16384
#define SMEM_FLOATS (2 * NB * PADK + KT * 128 + NB * Hh)

__global__ __launch_bounds__(256, 1)
void lstm_kernel(const float* __restrict__ x,     // [8192][32][2]
                 const float* __restrict__ fc_b,  // [128]
                 float* __restrict__ out) {       // [8192][32][128]
    extern __shared__ float sm[];
    float* Hbuf0 = sm;                         // [64][257]
    float* Hbuf1 = sm + NB * PADK;             // [64][257]
    float* Wp    = sm + 2 * NB * PADK;         // [KT][128]
    float* Cs    = Wp + KT * 128;              // [64][256]

    const int tx = threadIdx.x;
    const int ty = tx >> 5;        // 0..7  -> row group (one warp)
    const int tj = tx & 31;        // 0..31 -> j within chunk
    const int rowbase = ty * 8;
    const int r0 = blockIdx.x * NB;

    // zero h (buffer 0, incl. pads) and c
    for (int i = tx; i < NB * PADK; i += 256) Hbuf0[i] = 0.0f;
    for (int i = tx; i < NB * Hh;  i += 256) Cs[i] = 0.0f;
    __syncthreads();

    const float4 fb = *reinterpret_cast<const float4*>(fc_b + tj * 4);

#pragma unroll 1
    for (int l = 0; l < LSTEPS; ++l) {
        float* cur = (l & 1) ? Hbuf1 : Hbuf0;
        float* nxt = (l & 1) ? Hbuf0 : Hbuf1;

        // x inputs for this thread's 8 rows (warp-uniform loads)
        float x0[8], x1[8];
#pragma unroll
        for (int ri = 0; ri < 8; ++ri) {
            const float* xp = x + (size_t)(r0 + rowbase + ri) * (LSTEPS * 2) + l * 2;
            x0[ri] = __ldg(xp);
            x1[ri] = __ldg(xp + 1);
        }

        // ---- gates: 8 chunks of 128 permuted columns (= 32 j's x 4 gates) ----
#pragma unroll 1
        for (int m = 0; m < 8; ++m) {
            const int j = m * 32 + tj;
            const float4 wA = *reinterpret_cast<const float4*>(g_Wihp + j * 8);     // q0s0 q0s1 q1s0 q1s1
            const float4 wB = *reinterpret_cast<const float4*>(g_Wihp + j * 8 + 4); // q2s0 q2s1 q3s0 q3s1
            const float4 bs = *reinterpret_cast<const float4*>(g_bias + j * 4);

            float acc[8][4];
#pragma unroll
            for (int ri = 0; ri < 8; ++ri) {
                acc[ri][0] = bs.x + x0[ri] * wA.x + x1[ri] * wA.y;
                acc[ri][1] = bs.y + x0[ri] * wA.z + x1[ri] * wA.w;
                acc[ri][2] = bs.z + x0[ri] * wB.x + x1[ri] * wB.y;
                acc[ri][3] = bs.w + x0[ri] * wB.z + x1[ri] * wB.w;
            }

#pragma unroll 1
            for (int kt = 0; kt < Hh / KT; ++kt) {
                __syncthreads();
                // stage Wt[kt*64 .. +64)[m*128 .. +128) -> Wp (coalesced float4)
#pragma unroll
                for (int i = 0; i < 8; ++i) {
                    int e = (tx + i * 256) * 4;            // element 0..8191
                    int krow = e >> 7, col = e & 127;
                    *reinterpret_cast<float4*>(Wp + e) =
                        *reinterpret_cast<const float4*>(
                            g_Wt + (size_t)(kt * KT + krow) * FOURH + m * 128 + col);
                }
                __syncthreads();

#pragma unroll 16
                for (int kk = 0; kk < KT; ++kk) {
                    const int k = kt * KT + kk;
                    const float4 b = *reinterpret_cast<const float4*>(Wp + kk * 128 + tj * 4);
#pragma unroll
                    for (int ri = 0; ri < 8; ++ri) {
                        const float a = cur[(rowbase + ri) * PADK + k];  // broadcast LDS
                        acc[ri][0] += a * b.x;
                        acc[ri][1] += a * b.y;
                        acc[ri][2] += a * b.z;
                        acc[ri][3] += a * b.w;
                    }
                }
            }

            // nonlinearity + state update (gate order: i, f, g, o)
#pragma unroll
            for (int ri = 0; ri < 8; ++ri) {
                const int cidx = (rowbase + ri) * Hh + j;
                const float ig = sigf(acc[ri][0]);
                const float fg = sigf(acc[ri][1]);
                const float gg = tanhfast(acc[ri][2]);
                const float og = sigf(acc[ri][3]);
                const float cn = fg * Cs[cidx] + ig * gg;
                Cs[cidx] = cn;
                nxt[(rowbase + ri) * PADK + j] = og * tanhfast(cn);
            }
        }
        __syncthreads();  // all of nxt written before FC reads it

        // ---- FC: out[r][l][o] = h_new[r] . fc_w[o] + fc_b[o], o = tj*4 + q ----
        float facc[8][4];
#pragma unroll
        for (int ri = 0; ri < 8; ++ri) {
            facc[ri][0] = fb.x; facc[ri][1] = fb.y;
            facc[ri][2] = fb.z; facc[ri][3] = fb.w;
        }
#pragma unroll 1
        for (int kt = 0; kt < Hh / KT; ++kt) {
            __syncthreads();
#pragma unroll
            for (int i = 0; i < 8; ++i) {
                int e = (tx + i * 256) * 4;
                int krow = e >> 7, col = e & 127;
                *reinterpret_cast<float4*>(Wp + e) =
                    *reinterpret_cast<const float4*>(
                        g_fcT + (size_t)(kt * KT + krow) * OUTD + col);
            }
            __syncthreads();
#pragma unroll 16
            for (int kk = 0; kk < KT; ++kk) {
                const int k = kt * KT + kk;
                const float4 w = *reinterpret_cast<const float4*>(Wp + kk * 128 + tj * 4);
#pragma unroll
                for (int ri = 0; ri < 8; ++ri) {
                    const float a = nxt[(rowbase + ri) * PADK + k];
                    facc[ri][0] += a * w.x;
                    facc[ri][1] += a * w.y;
                    facc[ri][2] += a * w.z;
                    facc[ri][3] += a * w.w;
                }
            }
        }
#pragma unroll
        for (int ri = 0; ri < 8; ++ri) {
            const int n = r0 + rowbase + ri;
            float4 v;
            v.x = facc[ri][0]; v.y = facc[ri][1];
            v.z = facc[ri][2]; v.w = facc[ri][3];
            *reinterpret_cast<float4*>(out + (size_t)n * (LSTEPS * OUTD) + l * OUTD + tj * 4) = v;
        }
        // next iteration's first __syncthreads (panel stage) orders Wp/nxt reuse
    }
}

extern "C" void kernel_launch(void* const* d_in, const int* in_sizes, int n_in,
                              void* d_out, int out_size) {
    const float* x    = (const float*)d_in[0];
    const float* W_ih = (const float*)d_in[1];
    const float* W_hh = (const float*)d_in[2];
    const float* b_ih = (const float*)d_in[3];
    const float* b_hh = (const float*)d_in[4];
    const float* fc_w = (const float*)d_in[5];
    const float* fc_b = (const float*)d_in[6];
    float* out = (float*)d_out;

    prep_kernel<<<128, 256>>>(W_ih, W_hh, b_ih, b_hh, fc_w);

    const size_t smem_bytes = (size_t)SMEM_FLOATS * sizeof(float);  // 229,888 B
    cudaFuncSetAttribute(lstm_kernel, cudaFuncAttributeMaxDynamicSharedMemorySize,
                         (int)smem_bytes);
    lstm_kernel<<<NCTA, 256, smem_bytes>>>(x, fc_b, out);
}